// round 7
// baseline (speedup 1.0000x reference)
#include <cuda_runtime.h>
#include <cuda_fp16.h>
#include <cstdint>

#define BATCH 64
#define SEQ   512
#define ISZ   512
#define HSZ   1024
#define G4    4096
#define NCTA  128

// ---------- static device scratch ----------
__device__ __align__(16) __half g_x16[(size_t)BATCH * SEQ * ISZ];   // 32 MB
__device__ __align__(16) __half g_Wx16[(size_t)G4 * ISZ];           // 4 MB  [col][k]
__device__ __align__(16) __half g_Wh16[(size_t)NCTA * 32 * HSZ];    // 8 MB  [cta][p][k] (gate-permuted)
__device__ float  g_bias[G4];
__device__ __align__(16) __half g_gx16[(size_t)SEQ * NCTA * BATCH * 32]; // 268 MB [t][cta][b][32p]
__device__ __align__(16) __half g_h[2][BATCH * HSZ];
__device__ __align__(16) float  g_hT[BATCH * HSZ];
__device__ unsigned g_flag[NCTA];

// ---------- asm helpers ----------
__device__ __forceinline__ void mma16816(float d[4],
    uint32_t a0, uint32_t a1, uint32_t a2, uint32_t a3, uint32_t b0, uint32_t b1) {
  asm volatile(
    "mma.sync.aligned.m16n8k16.row.col.f32.f16.f16.f32 "
    "{%0,%1,%2,%3}, {%4,%5,%6,%7}, {%8,%9}, {%0,%1,%2,%3};\n"
    : "+f"(d[0]), "+f"(d[1]), "+f"(d[2]), "+f"(d[3])
    : "r"(a0), "r"(a1), "r"(a2), "r"(a3), "r"(b0), "r"(b1));
}
__device__ __forceinline__ void ldsm4(uint32_t& r0, uint32_t& r1, uint32_t& r2,
                                      uint32_t& r3, uint32_t addr) {
  asm volatile("ldmatrix.sync.aligned.m8n8.x4.shared.b16 {%0,%1,%2,%3}, [%4];"
    : "=r"(r0), "=r"(r1), "=r"(r2), "=r"(r3) : "r"(addr));
}
__device__ __forceinline__ void cp16(uint32_t smem, const void* g) {
  asm volatile("cp.async.cg.shared.global [%0], [%1], 16;" :: "r"(smem), "l"(g));
}
__device__ __forceinline__ void cp_commit() { asm volatile("cp.async.commit_group;"); }
template <int N> __device__ __forceinline__ void cp_wait() {
  asm volatile("cp.async.wait_group %0;" :: "n"(N));
}
__device__ __forceinline__ unsigned ld_acq(const unsigned* p) {
  unsigned v;
  asm volatile("ld.acquire.gpu.global.u32 %0, [%1];" : "=r"(v) : "l"(p));
  return v;
}
__device__ __forceinline__ void st_rel(unsigned* p, unsigned v) {
  asm volatile("st.release.gpu.global.u32 [%0], %1;" :: "l"(p), "r"(v));
}
// fast sigmoid / tanh via MUFU ex2 (__expf max err ~2 ulp)
__device__ __forceinline__ float fsig(float x) {
  x = fminf(fmaxf(x, -30.f), 30.f);
  return __fdividef(1.f, 1.f + __expf(-x));
}
__device__ __forceinline__ float ftanh(float x) {
  x = fminf(fmaxf(x, -15.f), 15.f);
  float e = __expf(2.f * x);
  return __fdividef(e - 1.f, e + 1.f);
}
// permuted column for (gate, unit): f->+0, i->+1, o->+8, g->+9
__device__ __forceinline__ int pcol(int gate, int u) {
  return ((u >> 2) << 4) + ((u & 3) << 1) + (gate & 1) + ((gate >> 1) << 3);
}

// ---------- init ----------
__global__ void k_init() {
  int i = blockIdx.x * blockDim.x + threadIdx.x;
  for (int idx = i; idx < BATCH * HSZ; idx += gridDim.x * blockDim.x)
    g_h[0][idx] = __float2half(0.f);
  if (i < NCTA) g_flag[i] = 0u;
}

// ---------- x -> fp16 ----------
__global__ void k_convx(const float* __restrict__ x) {
  size_t total4 = (size_t)BATCH * SEQ * ISZ / 4;
  for (size_t i = blockIdx.x * (size_t)blockDim.x + threadIdx.x; i < total4;
       i += (size_t)gridDim.x * blockDim.x) {
    float4 v = *(const float4*)(x + i * 4);
    __half2* dst = (__half2*)(g_x16 + i * 4);
    dst[0] = __floats2half2_rn(v.x, v.y);
    dst[1] = __floats2half2_rn(v.z, v.w);
  }
}

// ---------- weight prep ----------
__global__ void k_prep(const float* __restrict__ Wf, const float* __restrict__ Wfb,
                       const float* __restrict__ Wi, const float* __restrict__ Wib,
                       const float* __restrict__ Wo, const float* __restrict__ Wob,
                       const float* __restrict__ Wc, const float* __restrict__ Wcb) {
  int total = G4 * 1536;
  for (int idx = blockIdx.x * blockDim.x + threadIdx.x; idx < total;
       idx += gridDim.x * blockDim.x) {
    int col = idx / 1536, k = idx - (idx / 1536) * 1536;
    int gate = col >> 10, j = col & 1023;
    const float* Ws = (gate == 0) ? Wf : (gate == 1) ? Wi : (gate == 2) ? Wo : Wc;
    float v = Ws[(size_t)j * 1536 + k];
    if (k < ISZ) {
      g_Wx16[(size_t)col * ISZ + k] = __float2half(v);
    } else {
      int ct = j >> 3, u = j & 7;
      g_Wh16[((size_t)ct * 32 + pcol(gate, u)) * HSZ + (k - ISZ)] = __float2half(v);
    }
    if (k == 0) {
      const float* Bs = (gate == 0) ? Wfb : (gate == 1) ? Wib : (gate == 2) ? Wob : Wcb;
      g_bias[col] = Bs[j];
    }
  }
}

// ---------- gx = x @ Wx^T + b : pipelined, 2 CTAs/SM ----------
#define GXC 136
#define GX_STAGEH ((64 + 128) * GXC)           // halfs per stage
#define GX_SMEM (2 * GX_STAGEH * 2)            // 104448 bytes
__global__ void __launch_bounds__(256, 2) k_gemmx() {
  extern __shared__ __half sm[];
  const int t = blockIdx.y, col0 = blockIdx.x * 128, tid = threadIdx.x;
  const int lane = tid & 31, w = tid >> 5, gid = lane >> 2, tig = lane & 3;
  const int rb = 32 * (w & 1), cb = 32 * (w >> 1);

  // stage one 128-wide K-chunk: each row = 128 halfs = 16 x 16B units
  auto issue = [&](int c, int s) {
    __half* As = sm + s * GX_STAGEH;
    __half* Bs = As + 64 * GXC;
    #pragma unroll
    for (int it = 0; it < 4; ++it) {                 // 64 rows * 16 = 1024 units
      int u = it * 256 + tid, b = u >> 4, ko = (u & 15) * 8;
      cp16((uint32_t)__cvta_generic_to_shared(As + b * GXC + ko),
           g_x16 + ((size_t)b * SEQ + t) * ISZ + c * 128 + ko);
    }
    #pragma unroll
    for (int it = 0; it < 8; ++it) {                 // 128 rows * 16 = 2048 units
      int u = it * 256 + tid, cc = u >> 4, ko = (u & 15) * 8;
      cp16((uint32_t)__cvta_generic_to_shared(Bs + cc * GXC + ko),
           g_Wx16 + (size_t)(col0 + cc) * ISZ + c * 128 + ko);
    }
    cp_commit();
  };

  uint32_t a_ad[2], b_ad[2];
  {
    int row16 = lane & 15, koff = (lane >> 4) * 8;
    a_ad[0] = (uint32_t)__cvta_generic_to_shared(sm + (rb + row16) * GXC + koff);
    a_ad[1] = (uint32_t)__cvta_generic_to_shared(sm + (rb + 16 + row16) * GXC + koff);
    int j = lane >> 3, r = lane & 7;
    b_ad[0] = (uint32_t)__cvta_generic_to_shared(
        sm + 64 * GXC + (cb + (j >> 1) * 8 + r) * GXC + (j & 1) * 8);
    b_ad[1] = (uint32_t)__cvta_generic_to_shared(
        sm + 64 * GXC + (cb + 16 + (j >> 1) * 8 + r) * GXC + (j & 1) * 8);
  }

  float acc[2][4][4];
  #pragma unroll
  for (int m = 0; m < 2; m++)
    #pragma unroll
    for (int n = 0; n < 4; n++)
      #pragma unroll
      for (int q = 0; q < 4; q++) acc[m][n][q] = 0.f;

  issue(0, 0);
  #pragma unroll
  for (int c = 0; c < 4; ++c) {
    if (c < 3) { issue(c + 1, (c + 1) & 1); cp_wait<1>(); }
    else       { cp_wait<0>(); }
    __syncthreads();
    uint32_t so = (uint32_t)((c & 1) * GX_STAGEH * 2);  // stage byte offset
    #pragma unroll
    for (int kk = 0; kk < 8; ++kk) {
      uint32_t kb = so + kk * 32;
      uint32_t a[2][4], b[4][2];
      ldsm4(a[0][0], a[0][1], a[0][2], a[0][3], a_ad[0] + kb);
      ldsm4(a[1][0], a[1][1], a[1][2], a[1][3], a_ad[1] + kb);
      ldsm4(b[0][0], b[0][1], b[1][0], b[1][1], b_ad[0] + kb);
      ldsm4(b[2][0], b[2][1], b[3][0], b[3][1], b_ad[1] + kb);
      #pragma unroll
      for (int m = 0; m < 2; m++)
        #pragma unroll
        for (int n = 0; n < 4; n++)
          mma16816(acc[m][n], a[m][0], a[m][1], a[m][2], a[m][3], b[n][0], b[n][1]);
    }
    __syncthreads();
  }

  // epilogue: + bias, fp16, gate-permuted layout [t][ct][row][32]
  #pragma unroll
  for (int m = 0; m < 2; m++) {
    #pragma unroll
    for (int n = 0; n < 4; n++) {
      int row = rb + m * 16 + gid;
      #pragma unroll
      for (int v = 0; v < 4; v++) {
        int gcol = col0 + cb + n * 8 + tig * 2 + (v & 1);
        int r = row + (v >> 1) * 8;
        int gate = gcol >> 10, j = gcol & 1023, ct = j >> 3, u = j & 7;
        g_gx16[((size_t)t * NCTA + ct) * 2048 + r * 32 + pcol(gate, u)] =
            __float2half(acc[m][n][v] + g_bias[gcol]);
      }
    }
  }
}

// ---------- persistent recurrence: 128 CTAs x 256 threads ----------
// CTA owns 8 hidden units (32 permuted gate cols). Wh resident in SMEM.
// Thread (w,lane) owns rows r0,r0+8 and unit u with ALL 4 gates in its acc
// fragment -> pointwise update fully in registers, c in 2 registers.
#define LSTM_SMEM ((64 + 32) * 1032 * 2)
__global__ void __launch_bounds__(256, 1) k_lstm() {
  extern __shared__ char smraw[];
  __half* h_sm = (__half*)smraw;                    // [64][1032]
  __half* w_sm = (__half*)(smraw + 64 * 1032 * 2);  // [32][1032]

  const int tid = threadIdx.x, cta = blockIdx.x;
  const int lane = tid & 31, w = tid >> 5, gid = lane >> 2, tig = lane & 3;
  const int mblk = w & 3, nh = w >> 2, n0 = nh * 16;
  const int r0 = mblk * 16 + gid, r1 = r0 + 8;
  const int u = nh * 4 + tig, gu = cta * 8 + u;
  const int cbase = n0 + 2 * tig;

  // persistent Wh slice: 32 x 1024 halfs (64 KB)
  {
    const uint4* src = (const uint4*)(g_Wh16 + (size_t)cta * 32 * HSZ);
    #pragma unroll
    for (int it = 0; it < 16; ++it) {
      int i8 = (tid + it * 256) * 8, r = i8 >> 10, k = i8 & 1023;
      *(uint4*)(w_sm + r * 1032 + k) = src[tid + it * 256];
    }
  }
  __syncthreads();

  uint32_t a_ad, b_ad;
  {
    int row16 = lane & 15, koff = (lane >> 4) * 8;
    a_ad = (uint32_t)__cvta_generic_to_shared(h_sm + (mblk * 16 + row16) * 1032 + koff);
    int j = lane >> 3, r = lane & 7;
    b_ad = (uint32_t)__cvta_generic_to_shared(
        w_sm + (n0 + (j >> 1) * 8 + r) * 1032 + (j & 1) * 8);
  }

  float c0 = 0.f, c1 = 0.f;

  for (int t = 0; t < SEQ; ++t) {
    int p = t & 1;

    // prefetch this step's gx (independent of the barrier)
    const __half* gxp = g_gx16 + ((size_t)t * NCTA + cta) * 2048;
    __half2 fi0 = *(const __half2*)(gxp + r0 * 32 + cbase);
    __half2 og0 = *(const __half2*)(gxp + r0 * 32 + cbase + 8);
    __half2 fi1 = *(const __half2*)(gxp + r1 * 32 + cbase);
    __half2 og1 = *(const __half2*)(gxp + r1 * 32 + cbase + 8);

    // wait for every CTA to finish step t-1
    if (t > 0) {
      if (tid < NCTA) {
        while (ld_acq(&g_flag[tid]) < (unsigned)t) { }
      }
      __syncthreads();
    }

    // stage h via cp.async.cg in 4 K-chunks of 256 (overlaps MMA below)
    const char* hsrc = (const char*)g_h[p];
    #pragma unroll
    for (int c = 0; c < 4; ++c) {
      #pragma unroll
      for (int it = 0; it < 8; ++it) {
        int i = it * 256 + tid;               // 2048 x 16B per chunk
        int b = i >> 5, koff = (i & 31) * 8;
        uint32_t dst = (uint32_t)__cvta_generic_to_shared(
            h_sm + b * 1032 + c * 256 + koff);
        cp16(dst, hsrc + (size_t)(b * 1024 + c * 256 + koff) * 2);
      }
      cp_commit();
    }

    float acc[2][4];
    #pragma unroll
    for (int n = 0; n < 2; n++)
      #pragma unroll
      for (int q = 0; q < 4; q++) acc[n][q] = 0.f;

    #pragma unroll
    for (int c = 0; c < 4; ++c) {
      if (c == 0) cp_wait<3>();
      else if (c == 1) cp_wait<2>();
      else if (c == 2) cp_wait<1>();
      else cp_wait<0>();
      __syncthreads();
      #pragma unroll
      for (int kk = 0; kk < 16; ++kk) {
        uint32_t kb = (uint32_t)(c * 512 + kk * 32);
        uint32_t a0, a1, a2, a3, b00, b01, b10, b11;
        ldsm4(a0, a1, a2, a3, a_ad + kb);
        ldsm4(b00, b01, b10, b11, b_ad + kb);
        mma16816(acc[0], a0, a1, a2, a3, b00, b01);
        mma16816(acc[1], a0, a1, a2, a3, b10, b11);
      }
    }

    // fused pointwise LSTM update — all in registers
    float f0 = fsig(acc[0][0] + __low2float(fi0));
    float i0 = fsig(acc[0][1] + __high2float(fi0));
    float o0 = fsig(acc[1][0] + __low2float(og0));
    float g0 = ftanh(acc[1][1] + __high2float(og0));
    c0 = f0 * c0 + i0 * g0;
    float h0 = o0 * ftanh(c0);

    float f1 = fsig(acc[0][2] + __low2float(fi1));
    float i1 = fsig(acc[0][3] + __high2float(fi1));
    float o1 = fsig(acc[1][2] + __low2float(og1));
    float g1 = ftanh(acc[1][3] + __high2float(og1));
    c1 = f1 * c1 + i1 * g1;
    float h1 = o1 * ftanh(c1);

    g_h[p ^ 1][r0 * HSZ + gu] = __float2half(h0);
    g_h[p ^ 1][r1 * HSZ + gu] = __float2half(h1);
    if (t == SEQ - 1) {
      g_hT[r0 * HSZ + gu] = h0;
      g_hT[r1 * HSZ + gu] = h1;
    }

    __threadfence();
    __syncthreads();
    if (tid == 0) st_rel(&g_flag[cta], (unsigned)(t + 1));
  }
}

// ---------- logits ----------
__global__ void k_logits(const float* __restrict__ ow, const float* __restrict__ ob,
                         float* __restrict__ out) {
  int b = blockIdx.x, tid = threadIdx.x, o = tid >> 5, lane = tid & 31;
  if (o >= 10) return;
  float s = 0.f;
  for (int k = lane; k < HSZ; k += 32) s += g_hT[b * HSZ + k] * ow[o * HSZ + k];
  #pragma unroll
  for (int d = 16; d > 0; d >>= 1) s += __shfl_down_sync(0xFFFFFFFF, s, d);
  if (lane == 0) out[b * 10 + o] = s + ob[o];
}

// ---------- host ----------
extern "C" void kernel_launch(void* const* d_in, const int* in_sizes, int n_in,
                              void* d_out, int out_size) {
  const float* x   = (const float*)d_in[0];
  const float* Wf  = (const float*)d_in[1];  const float* Wfb = (const float*)d_in[2];
  const float* Wi  = (const float*)d_in[3];  const float* Wib = (const float*)d_in[4];
  const float* Wo  = (const float*)d_in[5];  const float* Wob = (const float*)d_in[6];
  const float* Wc  = (const float*)d_in[7];  const float* Wcb = (const float*)d_in[8];
  const float* ow  = (const float*)d_in[9];  const float* ob  = (const float*)d_in[10];
  float* out = (float*)d_out;

  cudaFuncSetAttribute(k_gemmx, cudaFuncAttributeMaxDynamicSharedMemorySize, GX_SMEM);
  cudaFuncSetAttribute(k_lstm,  cudaFuncAttributeMaxDynamicSharedMemorySize, LSTM_SMEM);

  k_init<<<256, 256>>>();
  k_convx<<<4096, 256>>>(x);
  k_prep<<<8192, 256>>>(Wf, Wfb, Wi, Wib, Wo, Wob, Wc, Wcb);
  k_gemmx<<<dim3(32, SEQ), 256, GX_SMEM>>>();
  k_lstm<<<NCTA, 256, LSTM_SMEM>>>();
  k_logits<<<BATCH, 320>>>(ow, ob, out);
}

// round 8
// speedup vs baseline: 1.1110x; 1.1110x over previous
#include <cuda_runtime.h>
#include <cuda_fp16.h>
#include <cstdint>

#define BATCH 64
#define SEQ   512
#define ISZ   512
#define HSZ   1024
#define G4    4096
#define NCTA  128

// ---------- static device scratch ----------
__device__ __align__(16) __half g_x16[(size_t)BATCH * SEQ * ISZ];   // 32 MB
__device__ __align__(16) __half g_Wx16[(size_t)G4 * ISZ];           // 4 MB  [col][k]
__device__ __align__(16) __half g_Wh16[(size_t)NCTA * 32 * HSZ];    // 8 MB  [cta][p][k] (gate-permuted)
__device__ float  g_bias[G4];
__device__ __align__(16) __half g_gx16[(size_t)SEQ * NCTA * BATCH * 32]; // 268 MB [t][cta][b][32p]
__device__ __align__(16) __half g_h[2][BATCH * HSZ];
__device__ __align__(16) float  g_hT[BATCH * HSZ];
__device__ unsigned g_flag[NCTA];

// ---------- asm helpers ----------
__device__ __forceinline__ void mma16816(float d[4],
    uint32_t a0, uint32_t a1, uint32_t a2, uint32_t a3, uint32_t b0, uint32_t b1) {
  asm volatile(
    "mma.sync.aligned.m16n8k16.row.col.f32.f16.f16.f32 "
    "{%0,%1,%2,%3}, {%4,%5,%6,%7}, {%8,%9}, {%0,%1,%2,%3};\n"
    : "+f"(d[0]), "+f"(d[1]), "+f"(d[2]), "+f"(d[3])
    : "r"(a0), "r"(a1), "r"(a2), "r"(a3), "r"(b0), "r"(b1));
}
__device__ __forceinline__ void ldsm4(uint32_t& r0, uint32_t& r1, uint32_t& r2,
                                      uint32_t& r3, uint32_t addr) {
  asm volatile("ldmatrix.sync.aligned.m8n8.x4.shared.b16 {%0,%1,%2,%3}, [%4];"
    : "=r"(r0), "=r"(r1), "=r"(r2), "=r"(r3) : "r"(addr));
}
__device__ __forceinline__ void cp16(uint32_t smem, const void* g) {
  asm volatile("cp.async.cg.shared.global [%0], [%1], 16;" :: "r"(smem), "l"(g));
}
__device__ __forceinline__ void cp_commit() { asm volatile("cp.async.commit_group;"); }
template <int N> __device__ __forceinline__ void cp_wait() {
  asm volatile("cp.async.wait_group %0;" :: "n"(N));
}
__device__ __forceinline__ unsigned ld_acq(const unsigned* p) {
  unsigned v;
  asm volatile("ld.acquire.gpu.global.u32 %0, [%1];" : "=r"(v) : "l"(p));
  return v;
}
__device__ __forceinline__ void st_rel(unsigned* p, unsigned v) {
  asm volatile("st.release.gpu.global.u32 [%0], %1;" :: "l"(p), "r"(v));
}
// fast sigmoid / tanh via MUFU ex2 (__expf max err ~2 ulp)
__device__ __forceinline__ float fsig(float x) {
  x = fminf(fmaxf(x, -30.f), 30.f);
  return __fdividef(1.f, 1.f + __expf(-x));
}
__device__ __forceinline__ float ftanh(float x) {
  x = fminf(fmaxf(x, -15.f), 15.f);
  float e = __expf(2.f * x);
  return __fdividef(e - 1.f, e + 1.f);
}
// permuted column for (gate, unit): f->+0, i->+1, o->+8, g->+9
__device__ __forceinline__ int pcol(int gate, int u) {
  return ((u >> 2) << 4) + ((u & 3) << 1) + (gate & 1) + ((gate >> 1) << 3);
}

// ---------- init ----------
__global__ void k_init() {
  int i = blockIdx.x * blockDim.x + threadIdx.x;
  for (int idx = i; idx < BATCH * HSZ; idx += gridDim.x * blockDim.x)
    g_h[0][idx] = __float2half(0.f);
  if (i < NCTA) g_flag[i] = 0u;
}

// ---------- x -> fp16 ----------
__global__ void k_convx(const float* __restrict__ x) {
  size_t total4 = (size_t)BATCH * SEQ * ISZ / 4;
  for (size_t i = blockIdx.x * (size_t)blockDim.x + threadIdx.x; i < total4;
       i += (size_t)gridDim.x * blockDim.x) {
    float4 v = *(const float4*)(x + i * 4);
    __half2* dst = (__half2*)(g_x16 + i * 4);
    dst[0] = __floats2half2_rn(v.x, v.y);
    dst[1] = __floats2half2_rn(v.z, v.w);
  }
}

// ---------- weight prep ----------
__global__ void k_prep(const float* __restrict__ Wf, const float* __restrict__ Wfb,
                       const float* __restrict__ Wi, const float* __restrict__ Wib,
                       const float* __restrict__ Wo, const float* __restrict__ Wob,
                       const float* __restrict__ Wc, const float* __restrict__ Wcb) {
  int total = G4 * 1536;
  for (int idx = blockIdx.x * blockDim.x + threadIdx.x; idx < total;
       idx += gridDim.x * blockDim.x) {
    int col = idx / 1536, k = idx - (idx / 1536) * 1536;
    int gate = col >> 10, j = col & 1023;
    const float* Ws = (gate == 0) ? Wf : (gate == 1) ? Wi : (gate == 2) ? Wo : Wc;
    float v = Ws[(size_t)j * 1536 + k];
    if (k < ISZ) {
      g_Wx16[(size_t)col * ISZ + k] = __float2half(v);
    } else {
      int ct = j >> 3, u = j & 7;
      g_Wh16[((size_t)ct * 32 + pcol(gate, u)) * HSZ + (k - ISZ)] = __float2half(v);
    }
    if (k == 0) {
      const float* Bs = (gate == 0) ? Wfb : (gate == 1) ? Wib : (gate == 2) ? Wob : Wcb;
      g_bias[col] = Bs[j];
    }
  }
}

// ---------- gx = x @ Wx^T + b : pipelined, 2 CTAs/SM ----------
#define GXC 136
#define GX_STAGEH ((64 + 128) * GXC)           // halfs per stage
#define GX_SMEM (2 * GX_STAGEH * 2)            // 104448 bytes
__global__ void __launch_bounds__(256, 2) k_gemmx() {
  extern __shared__ __half sm[];
  const int t = blockIdx.y, col0 = blockIdx.x * 128, tid = threadIdx.x;
  const int lane = tid & 31, w = tid >> 5, gid = lane >> 2, tig = lane & 3;
  const int rb = 32 * (w & 1), cb = 32 * (w >> 1);

  // stage one 128-wide K-chunk: each row = 128 halfs = 16 x 16B units
  auto issue = [&](int c, int s) {
    __half* As = sm + s * GX_STAGEH;
    __half* Bs = As + 64 * GXC;
    #pragma unroll
    for (int it = 0; it < 4; ++it) {                 // 64 rows * 16 = 1024 units
      int u = it * 256 + tid, b = u >> 4, ko = (u & 15) * 8;
      cp16((uint32_t)__cvta_generic_to_shared(As + b * GXC + ko),
           g_x16 + ((size_t)b * SEQ + t) * ISZ + c * 128 + ko);
    }
    #pragma unroll
    for (int it = 0; it < 8; ++it) {                 // 128 rows * 16 = 2048 units
      int u = it * 256 + tid, cc = u >> 4, ko = (u & 15) * 8;
      cp16((uint32_t)__cvta_generic_to_shared(Bs + cc * GXC + ko),
           g_Wx16 + (size_t)(col0 + cc) * ISZ + c * 128 + ko);
    }
    cp_commit();
  };

  uint32_t a_ad[2], b_ad[2];
  {
    int row16 = lane & 15, koff = (lane >> 4) * 8;
    a_ad[0] = (uint32_t)__cvta_generic_to_shared(sm + (rb + row16) * GXC + koff);
    a_ad[1] = (uint32_t)__cvta_generic_to_shared(sm + (rb + 16 + row16) * GXC + koff);
    int j = lane >> 3, r = lane & 7;
    b_ad[0] = (uint32_t)__cvta_generic_to_shared(
        sm + 64 * GXC + (cb + (j >> 1) * 8 + r) * GXC + (j & 1) * 8);
    b_ad[1] = (uint32_t)__cvta_generic_to_shared(
        sm + 64 * GXC + (cb + 16 + (j >> 1) * 8 + r) * GXC + (j & 1) * 8);
  }

  float acc[2][4][4];
  #pragma unroll
  for (int m = 0; m < 2; m++)
    #pragma unroll
    for (int n = 0; n < 4; n++)
      #pragma unroll
      for (int q = 0; q < 4; q++) acc[m][n][q] = 0.f;

  issue(0, 0);
  #pragma unroll
  for (int c = 0; c < 4; ++c) {
    if (c < 3) { issue(c + 1, (c + 1) & 1); cp_wait<1>(); }
    else       { cp_wait<0>(); }
    __syncthreads();
    uint32_t so = (uint32_t)((c & 1) * GX_STAGEH * 2);  // stage byte offset
    #pragma unroll
    for (int kk = 0; kk < 8; ++kk) {
      uint32_t kb = so + kk * 32;
      uint32_t a[2][4], b[4][2];
      ldsm4(a[0][0], a[0][1], a[0][2], a[0][3], a_ad[0] + kb);
      ldsm4(a[1][0], a[1][1], a[1][2], a[1][3], a_ad[1] + kb);
      ldsm4(b[0][0], b[0][1], b[1][0], b[1][1], b_ad[0] + kb);
      ldsm4(b[2][0], b[2][1], b[3][0], b[3][1], b_ad[1] + kb);
      #pragma unroll
      for (int m = 0; m < 2; m++)
        #pragma unroll
        for (int n = 0; n < 4; n++)
          mma16816(acc[m][n], a[m][0], a[m][1], a[m][2], a[m][3], b[n][0], b[n][1]);
    }
    __syncthreads();
  }

  // epilogue: + bias, fp16, gate-permuted layout [t][ct][row][32]
  #pragma unroll
  for (int m = 0; m < 2; m++) {
    #pragma unroll
    for (int n = 0; n < 4; n++) {
      int row = rb + m * 16 + gid;
      #pragma unroll
      for (int v = 0; v < 4; v++) {
        int gcol = col0 + cb + n * 8 + tig * 2 + (v & 1);
        int r = row + (v >> 1) * 8;
        int gate = gcol >> 10, j = gcol & 1023, ct = j >> 3, u = j & 7;
        g_gx16[((size_t)t * NCTA + ct) * 2048 + r * 32 + pcol(gate, u)] =
            __float2half(acc[m][n][v] + g_bias[gcol]);
      }
    }
  }
}

// ---------- persistent recurrence: 128 CTAs x 256 threads ----------
// CTA owns 8 hidden units (32 permuted gate cols). Wh resident in SMEM.
// Thread (w,lane) owns rows r0,r0+8 and unit u with ALL 4 gates in its acc
// fragment -> pointwise update fully in registers, c in 2 registers.
#define LSTM_SMEM ((64 + 32) * 1032 * 2)
__global__ void __launch_bounds__(256, 1) k_lstm() {
  extern __shared__ char smraw[];
  __half* h_sm = (__half*)smraw;                    // [64][1032]
  __half* w_sm = (__half*)(smraw + 64 * 1032 * 2);  // [32][1032]

  const int tid = threadIdx.x, cta = blockIdx.x;
  const int lane = tid & 31, w = tid >> 5, gid = lane >> 2, tig = lane & 3;
  const int mblk = w & 3, nh = w >> 2, n0 = nh * 16;
  const int r0 = mblk * 16 + gid, r1 = r0 + 8;
  const int u = nh * 4 + tig, gu = cta * 8 + u;
  const int cbase = n0 + 2 * tig;

  // persistent Wh slice: 32 x 1024 halfs (64 KB)
  {
    const uint4* src = (const uint4*)(g_Wh16 + (size_t)cta * 32 * HSZ);
    #pragma unroll
    for (int it = 0; it < 16; ++it) {
      int i8 = (tid + it * 256) * 8, r = i8 >> 10, k = i8 & 1023;
      *(uint4*)(w_sm + r * 1032 + k) = src[tid + it * 256];
    }
  }
  __syncthreads();

  uint32_t a_ad, b_ad;
  {
    int row16 = lane & 15, koff = (lane >> 4) * 8;
    a_ad = (uint32_t)__cvta_generic_to_shared(h_sm + (mblk * 16 + row16) * 1032 + koff);
    int j = lane >> 3, r = lane & 7;
    b_ad = (uint32_t)__cvta_generic_to_shared(
        w_sm + (n0 + (j >> 1) * 8 + r) * 1032 + (j & 1) * 8);
  }

  float c0 = 0.f, c1 = 0.f;

  for (int t = 0; t < SEQ; ++t) {
    int p = t & 1;

    // prefetch this step's gx (independent of the barrier)
    const __half* gxp = g_gx16 + ((size_t)t * NCTA + cta) * 2048;
    __half2 fi0 = *(const __half2*)(gxp + r0 * 32 + cbase);
    __half2 og0 = *(const __half2*)(gxp + r0 * 32 + cbase + 8);
    __half2 fi1 = *(const __half2*)(gxp + r1 * 32 + cbase);
    __half2 og1 = *(const __half2*)(gxp + r1 * 32 + cbase + 8);

    // wait for every CTA to finish step t-1
    if (t > 0) {
      if (tid < NCTA) {
        while (ld_acq(&g_flag[tid]) < (unsigned)t) { }
      }
      __syncthreads();
    }

    // stage h via cp.async.cg in 4 K-chunks of 256 (overlaps MMA below)
    const char* hsrc = (const char*)g_h[p];
    #pragma unroll
    for (int c = 0; c < 4; ++c) {
      #pragma unroll
      for (int it = 0; it < 8; ++it) {
        int i = it * 256 + tid;               // 2048 x 16B per chunk
        int b = i >> 5, koff = (i & 31) * 8;
        uint32_t dst = (uint32_t)__cvta_generic_to_shared(
            h_sm + b * 1032 + c * 256 + koff);
        cp16(dst, hsrc + (size_t)(b * 1024 + c * 256 + koff) * 2);
      }
      cp_commit();
    }

    float acc[2][4];
    #pragma unroll
    for (int n = 0; n < 2; n++)
      #pragma unroll
      for (int q = 0; q < 4; q++) acc[n][q] = 0.f;

    #pragma unroll
    for (int c = 0; c < 4; ++c) {
      if (c == 0) cp_wait<3>();
      else if (c == 1) cp_wait<2>();
      else if (c == 2) cp_wait<1>();
      else cp_wait<0>();
      __syncthreads();
      #pragma unroll
      for (int kk = 0; kk < 16; ++kk) {
        uint32_t kb = (uint32_t)(c * 512 + kk * 32);
        uint32_t a0, a1, a2, a3, b00, b01, b10, b11;
        ldsm4(a0, a1, a2, a3, a_ad + kb);
        ldsm4(b00, b01, b10, b11, b_ad + kb);
        mma16816(acc[0], a0, a1, a2, a3, b00, b01);
        mma16816(acc[1], a0, a1, a2, a3, b10, b11);
      }
    }

    // fused pointwise LSTM update — all in registers
    float f0 = fsig(acc[0][0] + __low2float(fi0));
    float i0 = fsig(acc[0][1] + __high2float(fi0));
    float o0 = fsig(acc[1][0] + __low2float(og0));
    float g0 = ftanh(acc[1][1] + __high2float(og0));
    c0 = f0 * c0 + i0 * g0;
    float h0 = o0 * ftanh(c0);

    float f1 = fsig(acc[0][2] + __low2float(fi1));
    float i1 = fsig(acc[0][3] + __high2float(fi1));
    float o1 = fsig(acc[1][2] + __low2float(og1));
    float g1 = ftanh(acc[1][3] + __high2float(og1));
    c1 = f1 * c1 + i1 * g1;
    float h1 = o1 * ftanh(c1);

    g_h[p ^ 1][r0 * HSZ + gu] = __float2half(h0);
    g_h[p ^ 1][r1 * HSZ + gu] = __float2half(h1);
    if (t == SEQ - 1) {
      g_hT[r0 * HSZ + gu] = h0;
      g_hT[r1 * HSZ + gu] = h1;
    }

    // publish: CTA-barrier (acq_rel) + tid0 release-store — release
    // cumulativity covers all threads' h stores; no gpu-scope membar needed.
    __syncthreads();
    if (tid == 0) st_rel(&g_flag[cta], (unsigned)(t + 1));
  }
}

// ---------- logits ----------
__global__ void k_logits(const float* __restrict__ ow, const float* __restrict__ ob,
                         float* __restrict__ out) {
  int b = blockIdx.x, tid = threadIdx.x, o = tid >> 5, lane = tid & 31;
  if (o >= 10) return;
  float s = 0.f;
  for (int k = lane; k < HSZ; k += 32) s += g_hT[b * HSZ + k] * ow[o * HSZ + k];
  #pragma unroll
  for (int d = 16; d > 0; d >>= 1) s += __shfl_down_sync(0xFFFFFFFF, s, d);
  if (lane == 0) out[b * 10 + o] = s + ob[o];
}

// ---------- host ----------
extern "C" void kernel_launch(void* const* d_in, const int* in_sizes, int n_in,
                              void* d_out, int out_size) {
  const float* x   = (const float*)d_in[0];
  const float* Wf  = (const float*)d_in[1];  const float* Wfb = (const float*)d_in[2];
  const float* Wi  = (const float*)d_in[3];  const float* Wib = (const float*)d_in[4];
  const float* Wo  = (const float*)d_in[5];  const float* Wob = (const float*)d_in[6];
  const float* Wc  = (const float*)d_in[7];  const float* Wcb = (const float*)d_in[8];
  const float* ow  = (const float*)d_in[9];  const float* ob  = (const float*)d_in[10];
  float* out = (float*)d_out;

  cudaFuncSetAttribute(k_gemmx, cudaFuncAttributeMaxDynamicSharedMemorySize, GX_SMEM);
  cudaFuncSetAttribute(k_lstm,  cudaFuncAttributeMaxDynamicSharedMemorySize, LSTM_SMEM);

  k_init<<<256, 256>>>();
  k_convx<<<4096, 256>>>(x);
  k_prep<<<8192, 256>>>(Wf, Wfb, Wi, Wib, Wo, Wob, Wc, Wcb);
  k_gemmx<<<dim3(32, SEQ), 256, GX_SMEM>>>();
  k_lstm<<<NCTA, 256, LSTM_SMEM>>>();
  k_logits<<<BATCH, 320>>>(ow, ob, out);
}

// round 9
// speedup vs baseline: 1.5367x; 1.3832x over previous
#include <cuda_runtime.h>
#include <cuda_fp16.h>
#include <cstdint>

#define BATCH 64
#define SEQ   512
#define ISZ   512
#define HSZ   1024
#define G4    4096
#define NCTA  128

// ---------- static device scratch ----------
__device__ __align__(16) __half g_x16[(size_t)BATCH * SEQ * ISZ];   // 32 MB
__device__ __align__(16) __half g_Wx16[(size_t)G4 * ISZ];           // 4 MB  [col][k]
__device__ __align__(16) __half g_Wh16[(size_t)NCTA * 32 * HSZ];    // 8 MB  [cta][c][k]
__device__ float  g_bias[G4];
__device__ float  g_gx[(size_t)SEQ * NCTA * BATCH * 32];            // 536 MB [t][cta][b][32]
__device__ __align__(16) __half g_h[2][BATCH * HSZ];
__device__ __align__(16) float  g_hT[BATCH * HSZ];
__device__ unsigned g_flag[NCTA];

// ---------- asm helpers ----------
__device__ __forceinline__ void mma16816(float d[4],
    uint32_t a0, uint32_t a1, uint32_t a2, uint32_t a3, uint32_t b0, uint32_t b1) {
  asm volatile(
    "mma.sync.aligned.m16n8k16.row.col.f32.f16.f16.f32 "
    "{%0,%1,%2,%3}, {%4,%5,%6,%7}, {%8,%9}, {%0,%1,%2,%3};\n"
    : "+f"(d[0]), "+f"(d[1]), "+f"(d[2]), "+f"(d[3])
    : "r"(a0), "r"(a1), "r"(a2), "r"(a3), "r"(b0), "r"(b1));
}
__device__ __forceinline__ void ldsm4(uint32_t& r0, uint32_t& r1, uint32_t& r2,
                                      uint32_t& r3, uint32_t addr) {
  asm volatile("ldmatrix.sync.aligned.m8n8.x4.shared.b16 {%0,%1,%2,%3}, [%4];"
    : "=r"(r0), "=r"(r1), "=r"(r2), "=r"(r3) : "r"(addr));
}
__device__ __forceinline__ void cp16(uint32_t smem, const void* g) {
  asm volatile("cp.async.cg.shared.global [%0], [%1], 16;" :: "r"(smem), "l"(g));
}
__device__ __forceinline__ void cp_commit() { asm volatile("cp.async.commit_group;"); }
template <int N> __device__ __forceinline__ void cp_wait() {
  asm volatile("cp.async.wait_group %0;" :: "n"(N));
}
__device__ __forceinline__ unsigned ld_acq(const unsigned* p) {
  unsigned v;
  asm volatile("ld.acquire.gpu.global.u32 %0, [%1];" : "=r"(v) : "l"(p));
  return v;
}
__device__ __forceinline__ void st_rel(unsigned* p, unsigned v) {
  asm volatile("st.release.gpu.global.u32 [%0], %1;" :: "l"(p), "r"(v));
}
// fast sigmoid / tanh via MUFU ex2 (__expf max err ~2 ulp)
__device__ __forceinline__ float fsig(float x) {
  x = fminf(fmaxf(x, -30.f), 30.f);
  return __fdividef(1.f, 1.f + __expf(-x));
}
__device__ __forceinline__ float ftanh(float x) {
  x = fminf(fmaxf(x, -15.f), 15.f);
  float e = __expf(2.f * x);
  return __fdividef(e - 1.f, e + 1.f);
}

// ---------- init ----------
__global__ void k_init() {
  int i = blockIdx.x * blockDim.x + threadIdx.x;
  for (int idx = i; idx < BATCH * HSZ; idx += gridDim.x * blockDim.x)
    g_h[0][idx] = __float2half(0.f);
  if (i < NCTA) g_flag[i] = 0u;
}

// ---------- x -> fp16 ----------
__global__ void k_convx(const float* __restrict__ x) {
  size_t total4 = (size_t)BATCH * SEQ * ISZ / 4;
  for (size_t i = blockIdx.x * (size_t)blockDim.x + threadIdx.x; i < total4;
       i += (size_t)gridDim.x * blockDim.x) {
    float4 v = *(const float4*)(x + i * 4);
    __half2* dst = (__half2*)(g_x16 + i * 4);
    dst[0] = __floats2half2_rn(v.x, v.y);
    dst[1] = __floats2half2_rn(v.z, v.w);
  }
}

// ---------- weight prep ----------
__global__ void k_prep(const float* __restrict__ Wf, const float* __restrict__ Wfb,
                       const float* __restrict__ Wi, const float* __restrict__ Wib,
                       const float* __restrict__ Wo, const float* __restrict__ Wob,
                       const float* __restrict__ Wc, const float* __restrict__ Wcb) {
  int total = G4 * 1536;
  for (int idx = blockIdx.x * blockDim.x + threadIdx.x; idx < total;
       idx += gridDim.x * blockDim.x) {
    int col = idx / 1536, k = idx - (idx / 1536) * 1536;
    int gate = col >> 10, j = col & 1023;
    const float* Ws = (gate == 0) ? Wf : (gate == 1) ? Wi : (gate == 2) ? Wo : Wc;
    float v = Ws[(size_t)j * 1536 + k];
    if (k < ISZ) {
      g_Wx16[(size_t)col * ISZ + k] = __float2half(v);
    } else {
      int ct = j >> 3, u = j & 7, c = gate * 8 + u;
      g_Wh16[((size_t)ct * 32 + c) * HSZ + (k - ISZ)] = __float2half(v);
    }
    if (k == 0) {
      const float* Bs = (gate == 0) ? Wfb : (gate == 1) ? Wib : (gate == 2) ? Wob : Wcb;
      g_bias[col] = Bs[j];
    }
  }
}

// ---------- gx = x @ Wx^T + b : pipelined, 2 CTAs/SM, f32 output ----------
#define GXC 136
#define GX_STAGEH ((64 + 128) * GXC)           // halfs per stage
#define GX_SMEM (2 * GX_STAGEH * 2)            // 104448 bytes
__global__ void __launch_bounds__(256, 2) k_gemmx() {
  extern __shared__ __half sm[];
  const int t = blockIdx.y, col0 = blockIdx.x * 128, tid = threadIdx.x;
  const int lane = tid & 31, w = tid >> 5, gid = lane >> 2, tig = lane & 3;
  const int rb = 32 * (w & 1), cb = 32 * (w >> 1);

  // stage one 128-wide K-chunk: each row = 128 halfs = 16 x 16B units
  auto issue = [&](int c, int s) {
    __half* As = sm + s * GX_STAGEH;
    __half* Bs = As + 64 * GXC;
    #pragma unroll
    for (int it = 0; it < 4; ++it) {                 // 64 rows * 16 = 1024 units
      int u = it * 256 + tid, b = u >> 4, ko = (u & 15) * 8;
      cp16((uint32_t)__cvta_generic_to_shared(As + b * GXC + ko),
           g_x16 + ((size_t)b * SEQ + t) * ISZ + c * 128 + ko);
    }
    #pragma unroll
    for (int it = 0; it < 8; ++it) {                 // 128 rows * 16 = 2048 units
      int u = it * 256 + tid, cc = u >> 4, ko = (u & 15) * 8;
      cp16((uint32_t)__cvta_generic_to_shared(Bs + cc * GXC + ko),
           g_Wx16 + (size_t)(col0 + cc) * ISZ + c * 128 + ko);
    }
    cp_commit();
  };

  uint32_t a_ad[2], b_ad[2];
  {
    int row16 = lane & 15, koff = (lane >> 4) * 8;
    a_ad[0] = (uint32_t)__cvta_generic_to_shared(sm + (rb + row16) * GXC + koff);
    a_ad[1] = (uint32_t)__cvta_generic_to_shared(sm + (rb + 16 + row16) * GXC + koff);
    int j = lane >> 3, r = lane & 7;
    b_ad[0] = (uint32_t)__cvta_generic_to_shared(
        sm + 64 * GXC + (cb + (j >> 1) * 8 + r) * GXC + (j & 1) * 8);
    b_ad[1] = (uint32_t)__cvta_generic_to_shared(
        sm + 64 * GXC + (cb + 16 + (j >> 1) * 8 + r) * GXC + (j & 1) * 8);
  }

  float acc[2][4][4];
  #pragma unroll
  for (int m = 0; m < 2; m++)
    #pragma unroll
    for (int n = 0; n < 4; n++)
      #pragma unroll
      for (int q = 0; q < 4; q++) acc[m][n][q] = 0.f;

  issue(0, 0);
  #pragma unroll
  for (int c = 0; c < 4; ++c) {
    if (c < 3) { issue(c + 1, (c + 1) & 1); cp_wait<1>(); }
    else       { cp_wait<0>(); }
    __syncthreads();
    uint32_t so = (uint32_t)((c & 1) * GX_STAGEH * 2);  // stage byte offset
    #pragma unroll
    for (int kk = 0; kk < 8; ++kk) {
      uint32_t kb = so + kk * 32;
      uint32_t a[2][4], b[4][2];
      ldsm4(a[0][0], a[0][1], a[0][2], a[0][3], a_ad[0] + kb);
      ldsm4(a[1][0], a[1][1], a[1][2], a[1][3], a_ad[1] + kb);
      ldsm4(b[0][0], b[0][1], b[1][0], b[1][1], b_ad[0] + kb);
      ldsm4(b[2][0], b[2][1], b[3][0], b[3][1], b_ad[1] + kb);
      #pragma unroll
      for (int m = 0; m < 2; m++)
        #pragma unroll
        for (int n = 0; n < 4; n++)
          mma16816(acc[m][n], a[m][0], a[m][1], a[m][2], a[m][3], b[n][0], b[n][1]);
    }
    __syncthreads();
  }

  // epilogue: + bias, f32, layout [t][ct][row][32] with plain gate order
  #pragma unroll
  for (int m = 0; m < 2; m++) {
    #pragma unroll
    for (int n = 0; n < 4; n++) {
      int row = rb + m * 16 + gid;
      int gcol = col0 + cb + n * 8 + tig * 2;
      int gate = gcol >> 10, j = gcol & 1023, ct = j >> 3, u = j & 7;
      int c = gate * 8 + u;
      float b0 = g_bias[gcol], b1 = g_bias[gcol + 1];
      size_t base = ((size_t)t * NCTA + ct) * (BATCH * 32);
      float* o0 = g_gx + base + (size_t)row * 32 + c;
      o0[0] = acc[m][n][0] + b0;  o0[1] = acc[m][n][1] + b1;
      float* o1 = g_gx + base + (size_t)(row + 8) * 32 + c;
      o1[0] = acc[m][n][2] + b0;  o1[1] = acc[m][n][3] + b1;
    }
  }
}

// ---------- persistent recurrence: 128 CTAs x 256 threads (R5 structure) ----------
#define LSTM_SMEM (64 * 1032 * 2 + 32 * 1032 * 2 + 64 * 33 * 4 + 512 * 4)
__global__ void __launch_bounds__(256, 1) k_lstm() {
  extern __shared__ char smraw[];
  __half* h_sm  = (__half*)smraw;                            // [64][1032]
  __half* w_sm  = (__half*)(smraw + 64 * 1032 * 2);          // [32][1032]
  float*  gates = (float*)(smraw + (64 + 32) * 1032 * 2);    // [64][33]
  float*  c_sm  = gates + 64 * 33;                           // [8][64] u*64+b

  const int tid = threadIdx.x, cta = blockIdx.x;
  const int lane = tid & 31, w = tid >> 5;
  const int gid = lane >> 2, tig = lane & 3;
  const int mblk = w & 3, n0 = (w >> 2) * 16;

  // persistent Wh slice: 32 x 1024 halfs (64 KB)
  {
    const uint4* src = (const uint4*)(g_Wh16 + (size_t)cta * 32 * HSZ);
    #pragma unroll
    for (int it = 0; it < 16; ++it) {
      int i8 = (tid + it * 256) * 8, r = i8 >> 10, k = i8 & 1023;
      *(uint4*)(w_sm + r * 1032 + k) = src[tid + it * 256];
    }
  }
  for (int i = tid; i < 512; i += 256) c_sm[i] = 0.f;
  __syncthreads();

  // ldmatrix base addresses
  uint32_t a_ad, b_ad;
  {
    int row16 = lane & 15, koff = (lane >> 4) * 8;
    a_ad = (uint32_t)__cvta_generic_to_shared(h_sm + (mblk * 16 + row16) * 1032 + koff);
    int j = lane >> 3, r = lane & 7;
    b_ad = (uint32_t)__cvta_generic_to_shared(
        w_sm + (n0 + (j >> 1) * 8 + r) * 1032 + (j & 1) * 8);
  }

  const int pb = tid & 63, pu = (tid >> 6) * 2;   // pointwise (batch, unit-pair)

  for (int t = 0; t < SEQ; ++t) {
    int p = t & 1;

    // prefetch gx for this step (independent of the barrier)
    const float* gxp = g_gx + ((size_t)t * NCTA + cta) * (BATCH * 32) + pb * 32 + pu;
    float2 gf = *(const float2*)(gxp + 0);
    float2 gi = *(const float2*)(gxp + 8);
    float2 go = *(const float2*)(gxp + 16);
    float2 gg = *(const float2*)(gxp + 24);

    // wait for every CTA to finish step t-1 (acquire)
    if (t > 0) {
      if (tid < NCTA) {
        while (ld_acq(&g_flag[tid]) < (unsigned)t) { }
      }
      __syncthreads();
    }

    // stage h via cp.async.cg in 4 K-chunks of 256 (overlaps with MMA below)
    const char* hsrc = (const char*)g_h[p];
    #pragma unroll
    for (int c = 0; c < 4; ++c) {
      #pragma unroll
      for (int it = 0; it < 8; ++it) {
        int i = it * 256 + tid;                  // 2048 x 16B units per chunk
        int b = i >> 5, koff = (i & 31) * 8;
        uint32_t dst = (uint32_t)__cvta_generic_to_shared(
            h_sm + b * 1032 + c * 256 + koff);
        cp16(dst, hsrc + (size_t)(b * 1024 + c * 256 + koff) * 2);
      }
      cp_commit();
    }

    float acc[2][4];
    #pragma unroll
    for (int n = 0; n < 2; n++)
      #pragma unroll
      for (int q = 0; q < 4; q++) acc[n][q] = 0.f;

    #pragma unroll
    for (int c = 0; c < 4; ++c) {
      if (c == 0) cp_wait<3>();
      else if (c == 1) cp_wait<2>();
      else if (c == 2) cp_wait<1>();
      else cp_wait<0>();
      __syncthreads();
      #pragma unroll
      for (int kk = 0; kk < 16; ++kk) {
        uint32_t kb = (uint32_t)(c * 512 + kk * 32);
        uint32_t a0, a1, a2, a3, b00, b01, b10, b11;
        ldsm4(a0, a1, a2, a3, a_ad + kb);
        ldsm4(b00, b01, b10, b11, b_ad + kb);
        mma16816(acc[0], a0, a1, a2, a3, b00, b01);
        mma16816(acc[1], a0, a1, a2, a3, b10, b11);
      }
    }

    // exchange gate partials via SMEM (each warp owns 16 of the 32 cols)
    #pragma unroll
    for (int hh = 0; hh < 2; ++hh) {
      int r = mblk * 16 + gid + hh * 8;
      gates[r * 33 + n0 + 2 * tig]         = acc[0][hh * 2 + 0];
      gates[r * 33 + n0 + 2 * tig + 1]     = acc[0][hh * 2 + 1];
      gates[r * 33 + n0 + 8 + 2 * tig]     = acc[1][hh * 2 + 0];
      gates[r * 33 + n0 + 8 + 2 * tig + 1] = acc[1][hh * 2 + 1];
    }
    __syncthreads();

    // fused pointwise LSTM update: thread handles (pb, pu) and (pb, pu+1)
    float hv[2];
    #pragma unroll
    for (int q = 0; q < 2; ++q) {
      int u = pu + q;
      float fg = fsig(gates[pb * 33 + u]       + (q ? gf.y : gf.x));
      float ig = fsig(gates[pb * 33 + 8 + u]   + (q ? gi.y : gi.x));
      float og = fsig(gates[pb * 33 + 16 + u]  + (q ? go.y : go.x));
      float cg = ftanh(gates[pb * 33 + 24 + u] + (q ? gg.y : gg.x));
      float cn = fg * c_sm[u * 64 + pb] + ig * cg;
      c_sm[u * 64 + pb] = cn;
      hv[q] = og * ftanh(cn);
    }
    *(__half2*)(g_h[p ^ 1] + pb * HSZ + cta * 8 + pu) = __floats2half2_rn(hv[0], hv[1]);
    if (t == SEQ - 1)
      *(float2*)(g_hT + pb * HSZ + cta * 8 + pu) = make_float2(hv[0], hv[1]);

    // publish (release); CTA barrier + release-store carry visibility
    __syncthreads();
    if (tid == 0) st_rel(&g_flag[cta], (unsigned)(t + 1));
  }
}

// ---------- logits ----------
__global__ void k_logits(const float* __restrict__ ow, const float* __restrict__ ob,
                         float* __restrict__ out) {
  int b = blockIdx.x, tid = threadIdx.x, o = tid >> 5, lane = tid & 31;
  if (o >= 10) return;
  float s = 0.f;
  for (int k = lane; k < HSZ; k += 32) s += g_hT[b * HSZ + k] * ow[o * HSZ + k];
  #pragma unroll
  for (int d = 16; d > 0; d >>= 1) s += __shfl_down_sync(0xFFFFFFFF, s, d);
  if (lane == 0) out[b * 10 + o] = s + ob[o];
}

// ---------- host ----------
extern "C" void kernel_launch(void* const* d_in, const int* in_sizes, int n_in,
                              void* d_out, int out_size) {
  const float* x   = (const float*)d_in[0];
  const float* Wf  = (const float*)d_in[1];  const float* Wfb = (const float*)d_in[2];
  const float* Wi  = (const float*)d_in[3];  const float* Wib = (const float*)d_in[4];
  const float* Wo  = (const float*)d_in[5];  const float* Wob = (const float*)d_in[6];
  const float* Wc  = (const float*)d_in[7];  const float* Wcb = (const float*)d_in[8];
  const float* ow  = (const float*)d_in[9];  const float* ob  = (const float*)d_in[10];
  float* out = (float*)d_out;

  cudaFuncSetAttribute(k_gemmx, cudaFuncAttributeMaxDynamicSharedMemorySize, GX_SMEM);
  cudaFuncSetAttribute(k_lstm,  cudaFuncAttributeMaxDynamicSharedMemorySize, LSTM_SMEM);

  k_init<<<256, 256>>>();
  k_convx<<<4096, 256>>>(x);
  k_prep<<<8192, 256>>>(Wf, Wfb, Wi, Wib, Wo, Wob, Wc, Wcb);
  k_gemmx<<<dim3(32, SEQ), 256, GX_SMEM>>>();
  k_lstm<<<NCTA, 256, LSTM_SMEM>>>();
  k_logits<<<BATCH, 320>>>(ow, ob, out);
}